// round 8
// baseline (speedup 1.0000x reference)
#include <cuda_runtime.h>
#include <cuda_bf16.h>
#include <math.h>
#include <stdint.h>

#define V_SZ 50280
#define DM   768
#define NL   4
#define DS   16
#define DC   4
#define DTR  48
#define ROH  512
#define DI   1536
#define BB   2
#define LL   128
#define MM   (BB*LL)        // 256
#define LBLK (DI*DS)        // 24576
#define FEATK (NL*LBLK)     // 98304

// ---------------- scratch (device globals; no allocation allowed) ----------------
__device__ __align__(128) float g_x[MM*DM];
__device__ __align__(128) float g_xz[MM*2*DI];
__device__ __align__(128) float g_xconv[MM*DI];
__device__ __align__(128) float g_dbc[MM*80];
__device__ __align__(128) float g_delta[MM*DI];
__device__ __align__(128) float g_h1[MM*ROH];
__device__ __align__(128) float g_h2[MM*(ROH/2)];

// 3-slot bf16 activations: per k -> (hi, hi, lo), row length 3K
__device__ __align__(128) __nv_bfloat16 g_xnb[MM*3*DM];
__device__ __align__(128) __nv_bfloat16 g_yb[MM*3*DI];
__device__ __align__(128) __nv_bfloat16 g_xfb[MM*3*DM];
__device__ __align__(128) __nv_bfloat16 g_h2b[MM*3*(ROH/2)];
__device__ __align__(128) __nv_bfloat16 g_featb[(size_t)MM*3*FEATK];   // ~151MB

// 3-slot bf16 weights: (3K, N) row-major, rows (3k,3k+1,3k+2) = (hi, lo, hi)
__device__ __align__(128) __nv_bfloat16 g_inpb[(size_t)NL*3*DM*2*DI];
__device__ __align__(128) __nv_bfloat16 g_outpb[(size_t)NL*3*DI*DM];
__device__ __align__(128) __nv_bfloat16 g_embb[(size_t)V_SZ*3*DM];     // (V, 3K) n-major
__device__ __align__(128) __nv_bfloat16 g_w1b[(size_t)3*FEATK*ROH];    // ~302MB
__device__ __align__(128) __nv_bfloat16 g_w3b[(size_t)3*(ROH/2)*V_SZ];

// ---------------- helpers ----------------
__device__ __forceinline__ uint32_t smem_u32(const void* p) {
    uint32_t a;
    asm("{ .reg .u64 t; cvta.to.shared.u64 t, %1; cvt.u32.u64 %0, t; }" : "=r"(a) : "l"(p));
    return a;
}
// A-side slots: (hi, hi, lo)
__device__ __forceinline__ void store3A(__nv_bfloat16* p, float v) {
    __nv_bfloat16 h = __float2bfloat16(v);
    __nv_bfloat16 l = __float2bfloat16(v - __bfloat162float(h));
    p[0] = h; p[1] = h; p[2] = l;
}
__device__ __forceinline__ void ldsm_x4(uint32_t* r, uint32_t addr) {
    asm volatile("ldmatrix.sync.aligned.m8n8.x4.shared.b16 {%0,%1,%2,%3}, [%4];"
        : "=r"(r[0]), "=r"(r[1]), "=r"(r[2]), "=r"(r[3]) : "r"(addr));
}
__device__ __forceinline__ void ldsm_x4t(uint32_t* r, uint32_t addr) {
    asm volatile("ldmatrix.sync.aligned.m8n8.x4.trans.shared.b16 {%0,%1,%2,%3}, [%4];"
        : "=r"(r[0]), "=r"(r[1]), "=r"(r[2]), "=r"(r[3]) : "r"(addr));
}
__device__ __forceinline__ void mma16816(float* c, const uint32_t* a, const uint32_t* b) {
    asm volatile(
        "mma.sync.aligned.m16n8k16.row.col.f32.bf16.bf16.f32 "
        "{%0,%1,%2,%3}, {%4,%5,%6,%7}, {%8,%9}, {%0,%1,%2,%3};"
        : "+f"(c[0]), "+f"(c[1]), "+f"(c[2]), "+f"(c[3])
        : "r"(a[0]), "r"(a[1]), "r"(a[2]), "r"(a[3]), "r"(b[0]), "r"(b[1]));
}
__device__ __forceinline__ void cpa16(uint32_t dst, const void* src, bool pred) {
    int sz = pred ? 16 : 0;
    asm volatile("cp.async.cg.shared.global [%0], [%1], 16, %2;"
        :: "r"(dst), "l"(src), "r"(sz) : "memory");
}
#define CP_COMMIT()  asm volatile("cp.async.commit_group;" ::: "memory")
#define CP_WAIT2()   asm volatile("cp.async.wait_group 2;" ::: "memory")

// ================= pipelined bf16 GEMM over K' = 3K =================
// C(256,N) (+)= A(256,K') * B.  BMAJ 0: B is (K',N) row-major (trans ldsm);
//                              BMAJ 1: B is (N,K') row-major (non-trans ldsm).
// flags: bit1 = atomicAdd epilogue. N boundary must align to 8. kps multiple of 64.
#define MSTR   144
#define ATILE  (256*MSTR)     // 36864
#define BTILE  (64*MSTR)      // 9216
#define STG    (ATILE+BTILE)  // 46080
#define MM2_DSM (4*STG)       // 184320

template<int BMAJ>
__global__ __launch_bounds__(256, 1)
void mm2(const __nv_bfloat16* __restrict__ A, int lda,
         const __nv_bfloat16* __restrict__ B, int ldb,
         float* __restrict__ C, int ldc,
         int N, int kps,
         const float* __restrict__ bias, int flags) {
    extern __shared__ char smem[];
    const uint32_t sb0 = smem_u32(smem);
    const int tid = threadIdx.x, lid = tid & 31, wid = tid >> 5;
    const int n0 = blockIdx.x * 64;
    const int kb = blockIdx.y * kps;
    const int nch = kps >> 6;

    float acc[2][8][4];
    #pragma unroll
    for (int i = 0; i < 2; i++)
        #pragma unroll
        for (int j = 0; j < 8; j++)
            #pragma unroll
            for (int k = 0; k < 4; k++) acc[i][j][k] = 0.f;

    auto load_stage = [&](int ic) {
        int k0 = kb + (ic << 6);
        uint32_t sb = sb0 + (ic & 3) * STG;
        #pragma unroll
        for (int it = 0; it < 8; it++) {
            int idx = it * 256 + tid;
            int row = idx >> 3, ch = idx & 7;
            cpa16(sb + row * MSTR + (ch << 4),
                  A + (size_t)row * lda + k0 + (ch << 3), true);
        }
        if (BMAJ == 0) {
            #pragma unroll
            for (int it = 0; it < 2; it++) {
                int idx = it * 256 + tid;
                int r = idx >> 3, ch = idx & 7;
                cpa16(sb + ATILE + r * MSTR + (ch << 4),
                      B + (size_t)(k0 + r) * ldb + n0 + (ch << 3),
                      (n0 + (ch << 3)) < N);
            }
        } else {
            #pragma unroll
            for (int it = 0; it < 2; it++) {
                int idx = it * 256 + tid;
                int r = idx >> 3, ch = idx & 7;
                cpa16(sb + ATILE + r * MSTR + (ch << 4),
                      B + (size_t)(n0 + r) * ldb + k0 + (ch << 3),
                      (n0 + r) < N);
            }
        }
        CP_COMMIT();
    };

    auto compute = [&](int buf) {
        const uint32_t sa = sb0 + buf * STG;
        const uint32_t sbB = sa + ATILE;
        #pragma unroll
        for (int k16 = 0; k16 < 4; k16++) {
            uint32_t a[2][4];
            #pragma unroll
            for (int mt = 0; mt < 2; mt++) {
                uint32_t aoff = (wid * 32 + mt * 16 + (lid & 15)) * MSTR
                              + (k16 << 5) + ((lid >> 4) << 4);
                ldsm_x4(a[mt], sa + aoff);
            }
            #pragma unroll
            for (int nh = 0; nh < 4; nh++) {
                uint32_t b4[4];
                if (BMAJ == 0) {
                    uint32_t boff = ((k16 << 4) + ((lid >> 3) & 1) * 8 + (lid & 7)) * MSTR
                                  + (nh << 5) + ((lid >> 4) << 4);
                    ldsm_x4t(b4, sbB + boff);
                } else {
                    uint32_t boff = (nh * 16 + (lid & 7) + ((lid >> 4) << 3)) * MSTR
                                  + (k16 << 5) + (((lid >> 3) & 1) << 4);
                    ldsm_x4(b4, sbB + boff);
                }
                #pragma unroll
                for (int mt = 0; mt < 2; mt++)
                    #pragma unroll
                    for (int j = 0; j < 2; j++)
                        mma16816(acc[mt][nh * 2 + j], a[mt], &b4[j * 2]);
            }
        }
    };

    #pragma unroll
    for (int s = 0; s < 3; s++) {
        if (s < nch) load_stage(s);
        else CP_COMMIT();
    }
    for (int ic = 0; ic < nch; ic++) {
        CP_WAIT2();
        __syncthreads();
        compute(ic & 3);
        __syncthreads();
        if (ic + 3 < nch) load_stage(ic + 3);
        else CP_COMMIT();
    }

    // epilogue
    #pragma unroll
    for (int mt = 0; mt < 2; mt++) {
        int r0 = wid * 32 + mt * 16 + (lid >> 2);
        #pragma unroll
        for (int nt = 0; nt < 8; nt++) {
            int col = n0 + nt * 8 + ((lid & 3) << 1);
            float* c = acc[mt][nt];
            if (flags & 2) {
                if (col < N) {
                    atomicAdd(&C[(size_t)r0 * ldc + col], c[0]);
                    atomicAdd(&C[(size_t)(r0 + 8) * ldc + col], c[2]);
                }
                if (col + 1 < N) {
                    atomicAdd(&C[(size_t)r0 * ldc + col + 1], c[1]);
                    atomicAdd(&C[(size_t)(r0 + 8) * ldc + col + 1], c[3]);
                }
            } else {
                if (col < N) {
                    float b0 = bias ? bias[col] : 0.f;
                    C[(size_t)r0 * ldc + col]       = c[0] + b0;
                    C[(size_t)(r0 + 8) * ldc + col] = c[2] + b0;
                }
                if (col + 1 < N) {
                    float b1 = bias ? bias[col + 1] : 0.f;
                    C[(size_t)r0 * ldc + col + 1]       = c[1] + b1;
                    C[(size_t)(r0 + 8) * ldc + col + 1] = c[3] + b1;
                }
            }
        }
    }
}

// ---------------- conversion kernels ----------------
// weights (K,N) fp32 -> (3K,N) bf16, rows (3k,3k+1,3k+2) = (hi, lo, hi)
__global__ void wconvKN(const float* __restrict__ in, __nv_bfloat16* __restrict__ out,
                        int K, int N) {
    size_t i = (size_t)blockIdx.x * 256 + threadIdx.x;
    if (i >= (size_t)K * N) return;
    int k = (int)(i / N), n = (int)(i % N);
    float v = in[i];
    __nv_bfloat16 h = __float2bfloat16(v);
    __nv_bfloat16 l = __float2bfloat16(v - __bfloat162float(h));
    out[(size_t)(3 * k)     * N + n] = h;
    out[(size_t)(3 * k + 1) * N + n] = l;
    out[(size_t)(3 * k + 2) * N + n] = h;
}
// embed (V,K) fp32 -> (V,3K) bf16, slots (hi, lo, hi) along K (B side, n-major)
__global__ void wconvNK(const float* __restrict__ in, __nv_bfloat16* __restrict__ out,
                        size_t total) {
    size_t i = (size_t)blockIdx.x * 256 + threadIdx.x;
    if (i >= total) return;
    float v = in[i];
    __nv_bfloat16 h = __float2bfloat16(v);
    __nv_bfloat16 l = __float2bfloat16(v - __bfloat162float(h));
    __nv_bfloat16* p = out + 3 * i;
    p[0] = h; p[1] = l; p[2] = h;
}
// relu + A-side 3-slot pack
__global__ void reluconv(const float* __restrict__ in, __nv_bfloat16* __restrict__ out, int n) {
    int i = blockIdx.x * 256 + threadIdx.x;
    if (i < n) store3A(out + 3 * (size_t)i, fmaxf(in[i], 0.f));
}

// ---------------- tiny utility kernels ----------------
__global__ void zero_kernel(float* p, int n) {
    int i = blockIdx.x*256 + threadIdx.x;
    if (i < n) p[i] = 0.f;
}
__global__ void binit_kernel(float* p, const float* __restrict__ bias, int rows, int cols) {
    int i = blockIdx.x*256 + threadIdx.x;
    if (i < rows*cols) p[i] = bias[i % cols];
}
__global__ void embed_kernel(const int* __restrict__ ids, const float* __restrict__ emb,
                             float* __restrict__ x) {
    int i = blockIdx.x*256 + threadIdx.x;
    if (i >= MM*DM) return;
    int m = i / DM, j = i % DM;
    x[i] = emb[(size_t)ids[m]*DM + j];
}
// rmsnorm -> A-side 3-slot bf16
__global__ void rmsnorm_pack(const float* __restrict__ x, const float* __restrict__ w,
                             __nv_bfloat16* __restrict__ out) {
    int m = blockIdx.x;
    const float* xr = x + (size_t)m*DM;
    float s = 0.f;
    for (int j = threadIdx.x; j < DM; j += blockDim.x) { float v = xr[j]; s += v*v; }
    __shared__ float red[32];
    int lane = threadIdx.x & 31, wid = threadIdx.x >> 5;
    #pragma unroll
    for (int o = 16; o > 0; o >>= 1) s += __shfl_down_sync(0xffffffffu, s, o);
    if (lane == 0) red[wid] = s;
    __syncthreads();
    if (wid == 0) {
        s = (lane < (int)(blockDim.x >> 5)) ? red[lane] : 0.f;
        #pragma unroll
        for (int o = 16; o > 0; o >>= 1) s += __shfl_down_sync(0xffffffffu, s, o);
        if (lane == 0) red[0] = s;
    }
    __syncthreads();
    float inv = rsqrtf(red[0]/(float)DM + 1e-5f);
    for (int j = threadIdx.x; j < DM; j += blockDim.x)
        store3A(out + ((size_t)m*DM + j)*3, xr[j]*inv*w[j]);
}
__global__ void conv_kernel(const float* __restrict__ xz, const float* __restrict__ cw,
                            const float* __restrict__ cb, float* __restrict__ xconv) {
    int i = blockIdx.x*256 + threadIdx.x;
    if (i >= MM*DI) return;
    int d = i % DI, m = i / DI, t = m % LL, b = m / LL;
    float acc = cb[d];
    #pragma unroll
    for (int k = 0; k < DC; k++) {
        int tt = t + k - (DC-1);
        if (tt >= 0) acc += cw[d*DC + k] * xz[(size_t)(b*LL + tt)*(2*DI) + d];
    }
    xconv[i] = acc / (1.f + __expf(-acc));   // silu
}

// ---------------- small FFMA GEMM (tiny shapes) ----------------
#define GBM 128
#define GBN 64
#define GBK 16
__global__ void gemm_kernel(const float* __restrict__ A, const float* __restrict__ B,
                            float* __restrict__ C, int M, int N, int K,
                            int lda, int ldb, int ldc,
                            const float* __restrict__ bias, int flags, int kPerSplit) {
    __shared__ __align__(16) float As[GBK][GBM];
    __shared__ __align__(16) float Bs[GBK][GBN];
    const int tid = threadIdx.x;
    const int m0 = blockIdx.y * GBM;
    const int n0 = blockIdx.x * GBN;
    const int kb = blockIdx.z * kPerSplit;
    const int ke = min(K, kb + kPerSplit);
    const bool arelu = flags & 1;
    float acc[8][4];
    #pragma unroll
    for (int i = 0; i < 8; i++)
        #pragma unroll
        for (int j = 0; j < 4; j++) acc[i][j] = 0.f;
    const int ty = tid >> 4, tx = tid & 15;
    for (int k0 = kb; k0 < ke; k0 += GBK) {
        #pragma unroll
        for (int r = 0; r < 2; r++) {
            int q  = tid + r*256;
            int m  = q >> 2;
            int kk = (q & 3) << 2;
            float4 v = make_float4(0.f, 0.f, 0.f, 0.f);
            if (m0 + m < M)
                v = *reinterpret_cast<const float4*>(A + (size_t)(m0+m)*lda + k0 + kk);
            if (arelu) { v.x = fmaxf(v.x,0.f); v.y = fmaxf(v.y,0.f);
                         v.z = fmaxf(v.z,0.f); v.w = fmaxf(v.w,0.f); }
            As[kk  ][m] = v.x; As[kk+1][m] = v.y; As[kk+2][m] = v.z; As[kk+3][m] = v.w;
        }
        #pragma unroll
        for (int i = 0; i < 4; i++) {
            int flat = i*256 + tid;
            int n = flat & 63;
            int k = flat >> 6;
            float v = 0.f;
            if (n0 + n < N) v = B[(size_t)(k0+k)*ldb + n0 + n];
            Bs[k][n] = v;
        }
        __syncthreads();
        #pragma unroll
        for (int k = 0; k < GBK; k++) {
            float4 a0 = *reinterpret_cast<const float4*>(&As[k][ty*8]);
            float4 a1 = *reinterpret_cast<const float4*>(&As[k][ty*8 + 4]);
            float4 b4 = *reinterpret_cast<const float4*>(&Bs[k][tx*4]);
            float av[8] = {a0.x,a0.y,a0.z,a0.w,a1.x,a1.y,a1.z,a1.w};
            float bv[4] = {b4.x,b4.y,b4.z,b4.w};
            #pragma unroll
            for (int i = 0; i < 8; i++)
                #pragma unroll
                for (int j = 0; j < 4; j++) acc[i][j] += av[i]*bv[j];
        }
        __syncthreads();
    }
    #pragma unroll
    for (int i = 0; i < 8; i++) {
        int row = m0 + ty*8 + i;
        if (row >= M) continue;
        #pragma unroll
        for (int j = 0; j < 4; j++) {
            int col = n0 + tx*4 + j;
            if (col >= N) continue;
            float v = acc[i][j];
            if (flags & 2) atomicAdd(&C[(size_t)row*ldc + col], v);
            else { if (bias) v += bias[col]; C[(size_t)row*ldc + col] = v; }
        }
    }
}

// ---------------- selective scan ----------------
__global__ void scan_kernel(const float* __restrict__ dbc,
                            const float* __restrict__ draw,
                            const float* __restrict__ xconv,
                            const float* __restrict__ xz,
                            const float* __restrict__ A_log_l,
                            const float* __restrict__ Dp_l,
                            __nv_bfloat16* __restrict__ yb,     // 3-slot (M, 3*DI)
                            float* __restrict__ hid,            // fp32 out (B,L,DI,DS)
                            __nv_bfloat16* __restrict__ featb,  // 3-slot (M, 3*FEATK)
                            int layer) {
    int n  = threadIdx.x & 15;
    int dl = threadIdx.x >> 4;
    int d  = blockIdx.x*16 + dl;
    int b  = blockIdx.y;
    float a  = -__expf(A_log_l[d*DS + n]);
    float Dv = Dp_l[d];
    float h = 0.f;
    for (int t = 0; t < LL; t++) {
        int m = b*LL + t;
        float dr = draw[m*DI + d];
        float delta = (dr > 20.f) ? dr : log1pf(__expf(dr));
        float xc = xconv[m*DI + d];
        float Bv = dbc[m*80 + DTR + n];
        float Cv = dbc[m*80 + DTR + DS + n];
        float dA = __expf(delta * a);
        h = fmaf(dA, h, delta*Bv*xc);
        hid[(size_t)m*LBLK + (size_t)d*DS + n] = h;
        store3A(featb + ((size_t)m*FEATK + (size_t)layer*LBLK + d*DS + n)*3, h);
        float p = h * Cv;
        p += __shfl_down_sync(0xffffffffu, p, 8, 16);
        p += __shfl_down_sync(0xffffffffu, p, 4, 16);
        p += __shfl_down_sync(0xffffffffu, p, 2, 16);
        p += __shfl_down_sync(0xffffffffu, p, 1, 16);
        if (n == 0) {
            float z = xz[(size_t)m*(2*DI) + DI + d];
            float sz = z / (1.f + __expf(-z));
            store3A(yb + ((size_t)m*DI + d)*3, (p + Dv*xc) * sz);
        }
    }
}

// ---------------- launcher ----------------
extern "C" void kernel_launch(void* const* d_in, const int* in_sizes, int n_in,
                              void* d_out, int out_size) {
    const int*   ids        = (const int*)  d_in[0];
    const float* emb        = (const float*)d_in[1];
    const float* norm_f     = (const float*)d_in[2];
    const float* norm_w     = (const float*)d_in[3];
    const float* in_proj_w  = (const float*)d_in[4];
    const float* conv_w     = (const float*)d_in[5];
    const float* conv_b     = (const float*)d_in[6];
    const float* x_proj_w   = (const float*)d_in[7];
    const float* dt_w       = (const float*)d_in[8];
    const float* dt_b       = (const float*)d_in[9];
    const float* A_log      = (const float*)d_in[10];
    const float* Dp         = (const float*)d_in[11];
    const float* out_proj_w = (const float*)d_in[12];
    const float* ro_w1      = (const float*)d_in[13];
    const float* ro_b1      = (const float*)d_in[14];
    const float* ro_w2      = (const float*)d_in[15];
    const float* ro_b2      = (const float*)d_in[16];
    const float* ro_w3      = (const float*)d_in[17];
    const float* ro_b3      = (const float*)d_in[18];

    float* out      = (float*)d_out;
    float* out_main = out;
    float* out_ro   = out + (size_t)BB*LL*V_SZ;
    float* out_hid  = out_ro + (size_t)BB*LL*V_SZ;

    float *px, *pxz, *pxconv, *pdbc, *pdelta, *ph1, *ph2;
    __nv_bfloat16 *pxnb, *pyb, *pxfb, *ph2b, *pfeatb;
    __nv_bfloat16 *pinpb, *poutpb, *pembb, *pw1b, *pw3b;
    cudaGetSymbolAddress((void**)&px,     g_x);
    cudaGetSymbolAddress((void**)&pxz,    g_xz);
    cudaGetSymbolAddress((void**)&pxconv, g_xconv);
    cudaGetSymbolAddress((void**)&pdbc,   g_dbc);
    cudaGetSymbolAddress((void**)&pdelta, g_delta);
    cudaGetSymbolAddress((void**)&ph1,    g_h1);
    cudaGetSymbolAddress((void**)&ph2,    g_h2);
    cudaGetSymbolAddress((void**)&pxnb,   g_xnb);
    cudaGetSymbolAddress((void**)&pyb,    g_yb);
    cudaGetSymbolAddress((void**)&pxfb,   g_xfb);
    cudaGetSymbolAddress((void**)&ph2b,   g_h2b);
    cudaGetSymbolAddress((void**)&pfeatb, g_featb);
    cudaGetSymbolAddress((void**)&pinpb,  g_inpb);
    cudaGetSymbolAddress((void**)&poutpb, g_outpb);
    cudaGetSymbolAddress((void**)&pembb,  g_embb);
    cudaGetSymbolAddress((void**)&pw1b,   g_w1b);
    cudaGetSymbolAddress((void**)&pw3b,   g_w3b);

    cudaFuncSetAttribute(mm2<0>, cudaFuncAttributeMaxDynamicSharedMemorySize, MM2_DSM);
    cudaFuncSetAttribute(mm2<1>, cudaFuncAttributeMaxDynamicSharedMemorySize, MM2_DSM);

    // ---- weight conversions (once per launch) ----
    {
        size_t n;
        n = (size_t)NL*DM*2*DI;
        wconvKN<<<(unsigned)((n + 255)/256), 256>>>(in_proj_w, pinpb, NL*DM, 2*DI);
        n = (size_t)NL*DI*DM;
        wconvKN<<<(unsigned)((n + 255)/256), 256>>>(out_proj_w, poutpb, NL*DI, DM);
        n = (size_t)FEATK*ROH;
        wconvKN<<<(unsigned)((n + 255)/256), 256>>>(ro_w1, pw1b, FEATK, ROH);
        n = (size_t)(ROH/2)*V_SZ;
        wconvKN<<<(unsigned)((n + 255)/256), 256>>>(ro_w3, pw3b, ROH/2, V_SZ);
        n = (size_t)V_SZ*DM;
        wconvNK<<<(unsigned)((n + 255)/256), 256>>>(emb, pembb, n);
    }

    embed_kernel<<<(MM*DM + 255)/256, 256>>>(ids, emb, px);

    for (int l = 0; l < NL; l++) {
        rmsnorm_pack<<<MM, 256>>>(px, norm_w + (size_t)l*DM, pxnb);

        // xz = xn @ in_proj   (K'=2304, split 4 x 576 -> 9 chunks, grid 192)
        zero_kernel<<<(MM*2*DI + 255)/256, 256>>>(pxz, MM*2*DI);
        mm2<0><<<dim3(48, 4), 256, MM2_DSM>>>(
            pxnb, 3*DM,
            pinpb + (size_t)l*3*DM*2*DI, 2*DI,
            pxz, 2*DI, 2*DI, 576, nullptr, 2);

        conv_kernel<<<(MM*DI + 255)/256, 256>>>(
            pxz, conv_w + (size_t)l*DI*DC, conv_b + (size_t)l*DI, pxconv);

        // dbc = xconv @ x_proj  (tiny: FFMA split-K=16)
        zero_kernel<<<(MM*80 + 255)/256, 256>>>(pdbc, MM*80);
        gemm_kernel<<<dim3(2, 2, 16), 256>>>(
            pxconv, x_proj_w + (size_t)l*DI*80, pdbc,
            MM, 80, DI, DI, 80, 80, nullptr, 2, 96);

        // delta_pre = dt @ dt_w + dt_b  (tiny: FFMA split-K=3, bias pre-init)
        binit_kernel<<<(MM*DI + 255)/256, 256>>>(pdelta, dt_b + (size_t)l*DI, MM, DI);
        gemm_kernel<<<dim3(24, 2, 3), 256>>>(
            pdbc, dt_w + (size_t)l*DTR*DI, pdelta,
            MM, DI, DTR, 80, DI, DI, nullptr, 2, 16);

        scan_kernel<<<dim3(DI/16, BB), 256>>>(
            pdbc, pdelta, pxconv, pxz,
            A_log + (size_t)l*DI*DS, Dp + (size_t)l*DI,
            pyb, out_hid + (size_t)l*MM*LBLK, pfeatb, l);

        // x += y @ out_proj   (K'=4608, split 12 x 384 -> 6 chunks, grid 144)
        mm2<0><<<dim3(12, 12), 256, MM2_DSM>>>(
            pyb, 3*DI,
            poutpb + (size_t)l*3*DI*DM, DM,
            px, DM, DM, 384, nullptr, 2);
    }

    // final norm + tied lm head (B = embb (V, 3K) n-major)
    rmsnorm_pack<<<MM, 256>>>(px, norm_f, pxfb);
    mm2<1><<<dim3((V_SZ + 63)/64, 1), 256, MM2_DSM>>>(
        pxfb, 3*DM,
        pembb, 3*DM,
        out_main, V_SZ, V_SZ, 3*DM, nullptr, 0);

    // readout: h1 = feat @ ro_w1 + b1 (K'=294912, split 24 x 12288 -> 192 chunks)
    binit_kernel<<<(MM*ROH + 255)/256, 256>>>(ph1, ro_b1, MM, ROH);
    mm2<0><<<dim3(8, 24), 256, MM2_DSM>>>(
        pfeatb, 3*FEATK,
        pw1b, ROH,
        ph1, ROH, ROH, 12288, nullptr, 2);

    // h2 = relu(h1) @ ro_w2 + b2  (tiny: FFMA, relu(A), atomic into bias-init)
    binit_kernel<<<(MM*(ROH/2) + 255)/256, 256>>>(ph2, ro_b2, MM, ROH/2);
    gemm_kernel<<<dim3(4, 2, 8), 256>>>(
        ph1, ro_w2, ph2, MM, ROH/2, ROH, ROH, ROH/2, ROH/2, nullptr, 3, 64);

    // pack relu(h2), then readout_logits = relu(h2) @ ro_w3 + b3  (K'=768, 12 chunks)
    reluconv<<<(MM*(ROH/2) + 255)/256, 256>>>(ph2, ph2b, MM*(ROH/2));
    mm2<0><<<dim3((V_SZ + 63)/64, 1), 256, MM2_DSM>>>(
        ph2b, 3*(ROH/2),
        pw3b, V_SZ,
        out_ro, V_SZ, V_SZ, 3*(ROH/2), ro_b3, 0);
}

// round 15
// speedup vs baseline: 1.1520x; 1.1520x over previous
#include <cuda_runtime.h>
#include <cuda_bf16.h>
#include <math.h>
#include <stdint.h>

#define V_SZ 50280
#define DM   768
#define NL   4
#define DS   16
#define DC   4
#define DTR  48
#define ROH  512
#define DI   1536
#define BB   2
#define LL   128
#define MM   (BB*LL)        // 256
#define LBLK (DI*DS)        // 24576
#define FEATK (NL*LBLK)     // 98304

// ---------------- scratch (device globals; no allocation allowed) ----------------
__device__ __align__(128) float g_x[MM*DM];
__device__ __align__(128) float g_xn[MM*DM];
__device__ __align__(128) float g_xz[MM*2*DI];
__device__ __align__(128) float g_xconv[MM*DI];
__device__ __align__(128) float g_dbc[MM*80];
__device__ __align__(128) float g_delta[MM*DI];
__device__ __align__(128) float g_y[MM*DI];
__device__ __align__(128) float g_h1[MM*ROH];
__device__ __align__(128) float g_h2[MM*(ROH/2)];
__device__ __align__(128) float g_xf[MM*DM];

// ---------------- helpers ----------------
__device__ __forceinline__ uint32_t smem_u32(const void* p) {
    uint32_t a;
    asm("{ .reg .u64 t; cvta.to.shared.u64 t, %1; cvt.u32.u64 %0, t; }" : "=r"(a) : "l"(p));
    return a;
}
// pack two floats to bf16x2: lo half = first arg
__device__ __forceinline__ uint32_t pk2(float lo, float hi) {
    uint32_t r;
    asm("cvt.rn.bf16x2.f32 %0, %1, %2;" : "=r"(r) : "f"(hi), "f"(lo));
    return r;
}
__device__ __forceinline__ void ldsm_x4(uint32_t* r, uint32_t addr) {
    asm volatile("ldmatrix.sync.aligned.m8n8.x4.shared.b16 {%0,%1,%2,%3}, [%4];"
        : "=r"(r[0]), "=r"(r[1]), "=r"(r[2]), "=r"(r[3]) : "r"(addr));
}
__device__ __forceinline__ void mma16816(float* c, const uint32_t* a, const uint32_t* b) {
    asm volatile(
        "mma.sync.aligned.m16n8k16.row.col.f32.bf16.bf16.f32 "
        "{%0,%1,%2,%3}, {%4,%5,%6,%7}, {%8,%9}, {%0,%1,%2,%3};"
        : "+f"(c[0]), "+f"(c[1]), "+f"(c[2]), "+f"(c[3])
        : "r"(a[0]), "r"(a[1]), "r"(a[2]), "r"(a[3]), "r"(b[0]), "r"(b[1]));
}
__device__ __forceinline__ void cpa16(uint32_t dst, const void* src) {
    asm volatile("cp.async.cg.shared.global [%0], [%1], 16;"
        :: "r"(dst), "l"(src) : "memory");
}
#define CP_COMMIT()   asm volatile("cp.async.commit_group;" ::: "memory")
#define CP_WAIT_1()   asm volatile("cp.async.wait_group 1;" ::: "memory")
#define CP_WAIT_ALL() asm volatile("cp.async.wait_group 0;" ::: "memory")

// ================= mm3: pipelined bf16x3 GEMM, fp32 operands, in-kernel conversion ===
// C(256,N) (+)= A(256,K) * B over fp32-K in chunks of 32 (bf16 K' = 96 per chunk).
// Slot encoding per k: A -> (h,h,l), B -> (h,l,h); dot = h*h + h*l + l*h (compensated).
// BSRC 0: B is (K,N) fp32 row-major.  BSRC 1: B is (N,K) fp32 row-major.
// ALAYERED: A is out_hid (NL, 256, LBLK) viewed as (256, NL*LBLK); kps must divide LBLK.
//           A uses layer-local K offsets; B keeps GLOBAL K offsets.
// flags: bit0 relu(A), bit1 atomicAdd epilogue.  N edge handled; kps multiple of 32.
#define F32STR  144
#define F32STG  (256*F32STR)          // 36864
#define BF16STR 208
#define BFB_OFF (256*BF16STR)         // 53248 (B region inside a bf16 stage)
#define BFSTG   (320*BF16STR)         // 66560
#define OFF_BF  (2*F32STG)            // 73728
#define MM3_DSM (OFF_BF + 2*BFSTG)    // 206848

template<int BSRC, int ALAYERED>
__global__ __launch_bounds__(256, 1)
void mm3(const float* __restrict__ A, int lda,
         const float* __restrict__ B, int ldb,
         float* __restrict__ C, int ldc,
         int N, int kps,
         const float* __restrict__ bias, int flags) {
    extern __shared__ char smem[];
    const uint32_t s0 = smem_u32(smem);
    const int tid = threadIdx.x, lid = tid & 31, wid = tid >> 5;
    const int n0 = blockIdx.x * 64;
    const int kbB = blockIdx.y * kps;   // global K base (B side)
    int kbA = kbB;                       // A-side K base (layer-local if ALAYERED)
    const int nch = kps >> 5;
    const bool arelu = flags & 1;

    const float* Ae = A;
    if (ALAYERED) { int l = kbB / LBLK; Ae = A + (size_t)l * MM * LBLK; kbA = kbB - l * LBLK; }

    float acc[2][8][4];
    #pragma unroll
    for (int i = 0; i < 2; i++)
        #pragma unroll
        for (int j = 0; j < 8; j++)
            #pragma unroll
            for (int k = 0; k < 4; k++) acc[i][j][k] = 0.f;

    float  bs[8];      // BSRC0 staging
    float4 bq[2];      // BSRC1 staging

    auto cpA = [&](int ic) {
        int k0 = kbA + (ic << 5);
        uint32_t dstb = s0 + (ic & 1) * F32STG;
        #pragma unroll
        for (int it = 0; it < 8; it++) {
            int idx = it * 256 + tid;
            int row = idx >> 3, ch = idx & 7;
            cpa16(dstb + row * F32STR + (ch << 4),
                  Ae + (size_t)row * lda + k0 + (ch << 2));
        }
        CP_COMMIT();
    };
    auto ldgB = [&](int ic) {
        int k0 = kbB + (ic << 5);
        if (BSRC == 0) {
            int n = tid & 63, kq = tid >> 6;
            bool ok = (n0 + n) < N;
            #pragma unroll
            for (int it = 0; it < 8; it++) {
                int k = kq * 8 + it;
                bs[it] = ok ? B[(size_t)(k0 + k) * ldb + n0 + n] : 0.f;
            }
        } else {
            #pragma unroll
            for (int it = 0; it < 2; it++) {
                int idx = it * 256 + tid;
                int n = idx >> 3, c = idx & 7;
                bq[it] = ((n0 + n) < N)
                    ? *(const float4*)(B + (size_t)(n0 + n) * ldb + k0 + (c << 2))
                    : make_float4(0.f, 0.f, 0.f, 0.f);
            }
        }
    };
    // convert chunk ic: fp32 stage -> bf16 3-slot stage (A: one row per thread)
    auto convA = [&](int ic) {
        const char* sp = smem + (ic & 1) * F32STG + tid * F32STR;
        char* dp = smem + OFF_BF + (ic & 1) * BFSTG + tid * BF16STR;
        #pragma unroll
        for (int q = 0; q < 8; q++) {
            float4 v = *(const float4*)(sp + (q << 4));
            if (arelu) { v.x = fmaxf(v.x, 0.f); v.y = fmaxf(v.y, 0.f);
                         v.z = fmaxf(v.z, 0.f); v.w = fmaxf(v.w, 0.f); }
            float ha = __bfloat162float(__float2bfloat16(v.x)), la = v.x - ha;
            float hb = __bfloat162float(__float2bfloat16(v.y)), lb = v.y - hb;
            float hc = __bfloat162float(__float2bfloat16(v.z)), lc = v.z - hc;
            float hd = __bfloat162float(__float2bfloat16(v.w)), ld = v.w - hd;
            // A slots (h,h,l): seq ha ha la hb hb lb hc hc lc hd hd ld
            uint2 p0 = make_uint2(pk2(ha, ha), pk2(la, hb));
            uint2 p1 = make_uint2(pk2(hb, lb), pk2(hc, hc));
            uint2 p2 = make_uint2(pk2(lc, hd), pk2(hd, ld));
            *(uint2*)(dp + 24 * q)      = p0;
            *(uint2*)(dp + 24 * q + 8)  = p1;
            *(uint2*)(dp + 24 * q + 16) = p2;
        }
    };
    auto convB = [&](int ic) {
        char* bbase = smem + OFF_BF + (ic & 1) * BFSTG + BFB_OFF;
        if (BSRC == 0) {
            int n = tid & 63, kq = tid >> 6;
            __nv_bfloat16* row = (__nv_bfloat16*)(bbase + n * BF16STR);
            #pragma unroll
            for (int it = 0; it < 8; it++) {
                int k = kq * 8 + it;
                float v = bs[it];
                __nv_bfloat16 hb16 = __float2bfloat16(v);
                float h = __bfloat162float(hb16);
                __nv_bfloat16 lb16 = __float2bfloat16(v - h);
                row[3 * k]     = hb16;   // B slots (h,l,h)
                row[3 * k + 1] = lb16;
                row[3 * k + 2] = hb16;
            }
        } else {
            #pragma unroll
            for (int it = 0; it < 2; it++) {
                int idx = it * 256 + tid;
                int n = idx >> 3, c = idx & 7;
                char* dp = bbase + n * BF16STR + 24 * c;
                float4 v = bq[it];
                float ha = __bfloat162float(__float2bfloat16(v.x)), la = v.x - ha;
                float hb = __bfloat162float(__float2bfloat16(v.y)), lb = v.y - hb;
                float hc = __bfloat162float(__float2bfloat16(v.z)), lc = v.z - hc;
                float hd = __bfloat162float(__float2bfloat16(v.w)), ld = v.w - hd;
                // B slots (h,l,h): seq ha la ha hb lb hb hc lc hc hd ld hd
                uint2 p0 = make_uint2(pk2(ha, la), pk2(ha, hb));
                uint2 p1 = make_uint2(pk2(lb, hb), pk2(hc, lc));
                uint2 p2 = make_uint2(pk2(hc, hd), pk2(ld, hd));
                *(uint2*)(dp)      = p0;
                *(uint2*)(dp + 8)  = p1;
                *(uint2*)(dp + 16) = p2;
            }
        }
    };
    auto compute = [&](int ic) {
        const uint32_t sa = s0 + OFF_BF + (ic & 1) * BFSTG;
        const uint32_t sb = sa + BFB_OFF;
        #pragma unroll
        for (int s = 0; s < 6; s++) {
            uint32_t a[2][4];
            #pragma unroll
            for (int mt = 0; mt < 2; mt++) {
                uint32_t aoff = (wid * 32 + mt * 16 + (lid & 15)) * BF16STR
                              + (s << 5) + ((lid >> 4) << 4);
                ldsm_x4(a[mt], sa + aoff);
            }
            #pragma unroll
            for (int nh = 0; nh < 4; nh++) {
                uint32_t b4[4];
                uint32_t boff = (nh * 16 + (lid & 7) + ((lid >> 4) << 3)) * BF16STR
                              + (s << 5) + (((lid >> 3) & 1) << 4);
                ldsm_x4(b4, sb + boff);
                #pragma unroll
                for (int mt = 0; mt < 2; mt++)
                    #pragma unroll
                    for (int j = 0; j < 2; j++)
                        mma16816(acc[mt][nh * 2 + j], a[mt], &b4[j * 2]);
            }
        }
    };

    // prologue (nch >= 2 in all launches)
    cpA(0);
    cpA(1);
    ldgB(0);
    CP_WAIT_1();               // chunk 0 fp32 arrived
    __syncthreads();
    convA(0); convB(0);
    ldgB(1);

    for (int ic = 0; ic < nch; ic++) {
        CP_WAIT_ALL();         // chunk ic+1 fp32 arrived (thread-local)
        __syncthreads();       // publish conv(ic) bf16 + fp32(ic+1) cross-thread
        if (ic + 2 < nch) cpA(ic + 2);
        compute(ic);           // same basic block as conversion below -> interleaved
        if (ic + 1 < nch) {
            convA(ic + 1); convB(ic + 1);
            if (ic + 2 < nch) ldgB(ic + 2);
        }
    }

    // epilogue
    #pragma unroll
    for (int mt = 0; mt < 2; mt++) {
        int r0 = wid * 32 + mt * 16 + (lid >> 2);
        #pragma unroll
        for (int nt = 0; nt < 8; nt++) {
            int col = n0 + nt * 8 + ((lid & 3) << 1);
            float* c = acc[mt][nt];
            if (flags & 2) {
                if (col < N) {
                    atomicAdd(&C[(size_t)r0 * ldc + col], c[0]);
                    atomicAdd(&C[(size_t)(r0 + 8) * ldc + col], c[2]);
                }
                if (col + 1 < N) {
                    atomicAdd(&C[(size_t)r0 * ldc + col + 1], c[1]);
                    atomicAdd(&C[(size_t)(r0 + 8) * ldc + col + 1], c[3]);
                }
            } else {
                if (col < N) {
                    float b0 = bias ? bias[col] : 0.f;
                    C[(size_t)r0 * ldc + col]       = c[0] + b0;
                    C[(size_t)(r0 + 8) * ldc + col] = c[2] + b0;
                }
                if (col + 1 < N) {
                    float b1 = bias ? bias[col + 1] : 0.f;
                    C[(size_t)r0 * ldc + col + 1]       = c[1] + b1;
                    C[(size_t)(r0 + 8) * ldc + col + 1] = c[3] + b1;
                }
            }
        }
    }
}

// ---------------- tiny utility kernels ----------------
__global__ void zero_kernel(float* p, int n) {
    int i = blockIdx.x*256 + threadIdx.x;
    if (i < n) p[i] = 0.f;
}
__global__ void binit_kernel(float* p, const float* __restrict__ bias, int rows, int cols) {
    int i = blockIdx.x*256 + threadIdx.x;
    if (i < rows*cols) p[i] = bias[i % cols];
}
__global__ void embed_kernel(const int* __restrict__ ids, const float* __restrict__ emb,
                             float* __restrict__ x) {
    int i = blockIdx.x*256 + threadIdx.x;
    if (i >= MM*DM) return;
    int m = i / DM, j = i % DM;
    x[i] = emb[(size_t)ids[m]*DM + j];
}
__global__ void rmsnorm_kernel(const float* __restrict__ x, const float* __restrict__ w,
                               float* __restrict__ out) {
    int m = blockIdx.x;
    const float* xr = x + (size_t)m*DM;
    float s = 0.f;
    for (int j = threadIdx.x; j < DM; j += blockDim.x) { float v = xr[j]; s += v*v; }
    __shared__ float red[32];
    int lane = threadIdx.x & 31, wid = threadIdx.x >> 5;
    #pragma unroll
    for (int o = 16; o > 0; o >>= 1) s += __shfl_down_sync(0xffffffffu, s, o);
    if (lane == 0) red[wid] = s;
    __syncthreads();
    if (wid == 0) {
        s = (lane < (int)(blockDim.x >> 5)) ? red[lane] : 0.f;
        #pragma unroll
        for (int o = 16; o > 0; o >>= 1) s += __shfl_down_sync(0xffffffffu, s, o);
        if (lane == 0) red[0] = s;
    }
    __syncthreads();
    float inv = rsqrtf(red[0]/(float)DM + 1e-5f);
    for (int j = threadIdx.x; j < DM; j += blockDim.x)
        out[(size_t)m*DM + j] = xr[j]*inv*w[j];
}
__global__ void conv_kernel(const float* __restrict__ xz, const float* __restrict__ cw,
                            const float* __restrict__ cb, float* __restrict__ xconv) {
    int i = blockIdx.x*256 + threadIdx.x;
    if (i >= MM*DI) return;
    int d = i % DI, m = i / DI, t = m % LL, b = m / LL;
    float acc = cb[d];
    #pragma unroll
    for (int k = 0; k < DC; k++) {
        int tt = t + k - (DC-1);
        if (tt >= 0) acc += cw[d*DC + k] * xz[(size_t)(b*LL + tt)*(2*DI) + d];
    }
    xconv[i] = acc / (1.f + __expf(-acc));   // silu
}

// ---------------- small FFMA GEMM (tiny shapes) ----------------
#define GBM 128
#define GBN 64
#define GBK 16
__global__ void gemm_kernel(const float* __restrict__ A, const float* __restrict__ B,
                            float* __restrict__ C, int M, int N, int K,
                            int lda, int ldb, int ldc,
                            const float* __restrict__ bias, int flags, int kPerSplit) {
    __shared__ __align__(16) float As[GBK][GBM];
    __shared__ __align__(16) float Bs[GBK][GBN];
    const int tid = threadIdx.x;
    const int m0 = blockIdx.y * GBM;
    const int n0 = blockIdx.x * GBN;
    const int kb = blockIdx.z * kPerSplit;
    const int ke = min(K, kb + kPerSplit);
    const bool arelu = flags & 1;
    float acc[8][4];
    #pragma unroll
    for (int i = 0; i < 8; i++)
        #pragma unroll
        for (int j = 0; j < 4; j++) acc[i][j] = 0.f;
    const int ty = tid >> 4, tx = tid & 15;
    for (int k0 = kb; k0 < ke; k0 += GBK) {
        #pragma unroll
        for (int r = 0; r < 2; r++) {
            int q  = tid + r*256;
            int m  = q >> 2;
            int kk = (q & 3) << 2;
            float4 v = make_float4(0.f, 0.f, 0.f, 0.f);
            if (m0 + m < M)
                v = *reinterpret_cast<const float4*>(A + (size_t)(m0+m)*lda + k0 + kk);
            if (arelu) { v.x = fmaxf(v.x,0.f); v.y = fmaxf(v.y,0.f);
                         v.z = fmaxf(v.z,0.f); v.w = fmaxf(v.w,0.f); }
            As[kk  ][m] = v.x; As[kk+1][m] = v.y; As[kk+2][m] = v.z; As[kk+3][m] = v.w;
        }
        #pragma unroll
        for (int i = 0; i < 4; i++) {
            int flat = i*256 + tid;
            int n = flat & 63;
            int k = flat >> 6;
            float v = 0.f;
            if (n0 + n < N) v = B[(size_t)(k0+k)*ldb + n0 + n];
            Bs[k][n] = v;
        }
        __syncthreads();
        #pragma unroll
        for (int k = 0; k < GBK; k++) {
            float4 a0 = *reinterpret_cast<const float4*>(&As[k][ty*8]);
            float4 a1 = *reinterpret_cast<const float4*>(&As[k][ty*8 + 4]);
            float4 b4 = *reinterpret_cast<const float4*>(&Bs[k][tx*4]);
            float av[8] = {a0.x,a0.y,a0.z,a0.w,a1.x,a1.y,a1.z,a1.w};
            float bv[4] = {b4.x,b4.y,b4.z,b4.w};
            #pragma unroll
            for (int i = 0; i < 8; i++)
                #pragma unroll
                for (int j = 0; j < 4; j++) acc[i][j] += av[i]*bv[j];
        }
        __syncthreads();
    }
    #pragma unroll
    for (int i = 0; i < 8; i++) {
        int row = m0 + ty*8 + i;
        if (row >= M) continue;
        #pragma unroll
        for (int j = 0; j < 4; j++) {
            int col = n0 + tx*4 + j;
            if (col >= N) continue;
            float v = acc[i][j];
            if (flags & 2) atomicAdd(&C[(size_t)row*ldc + col], v);
            else { if (bias) v += bias[col]; C[(size_t)row*ldc + col] = v; }
        }
    }
}

// ---------------- selective scan ----------------
__global__ void scan_kernel(const float* __restrict__ dbc,
                            const float* __restrict__ draw,
                            const float* __restrict__ xconv,
                            const float* __restrict__ xz,
                            const float* __restrict__ A_log_l,
                            const float* __restrict__ Dp_l,
                            float* __restrict__ y,
                            float* __restrict__ hid) {
    int n  = threadIdx.x & 15;
    int dl = threadIdx.x >> 4;
    int d  = blockIdx.x*16 + dl;
    int b  = blockIdx.y;
    float a  = -__expf(A_log_l[d*DS + n]);
    float Dv = Dp_l[d];
    float h = 0.f;
    for (int t = 0; t < LL; t++) {
        int m = b*LL + t;
        float dr = draw[m*DI + d];
        float delta = (dr > 20.f) ? dr : log1pf(__expf(dr));
        float xc = xconv[m*DI + d];
        float Bv = dbc[m*80 + DTR + n];
        float Cv = dbc[m*80 + DTR + DS + n];
        float dA = __expf(delta * a);
        h = fmaf(dA, h, delta*Bv*xc);
        hid[(size_t)m*LBLK + (size_t)d*DS + n] = h;
        float p = h * Cv;
        p += __shfl_down_sync(0xffffffffu, p, 8, 16);
        p += __shfl_down_sync(0xffffffffu, p, 4, 16);
        p += __shfl_down_sync(0xffffffffu, p, 2, 16);
        p += __shfl_down_sync(0xffffffffu, p, 1, 16);
        if (n == 0) {
            float z = xz[(size_t)m*(2*DI) + DI + d];
            float sz = z / (1.f + __expf(-z));
            y[m*DI + d] = (p + Dv*xc) * sz;
        }
    }
}

// ---------------- launcher ----------------
extern "C" void kernel_launch(void* const* d_in, const int* in_sizes, int n_in,
                              void* d_out, int out_size) {
    const int*   ids        = (const int*)  d_in[0];
    const float* emb        = (const float*)d_in[1];
    const float* norm_f     = (const float*)d_in[2];
    const float* norm_w     = (const float*)d_in[3];
    const float* in_proj_w  = (const float*)d_in[4];
    const float* conv_w     = (const float*)d_in[5];
    const float* conv_b     = (const float*)d_in[6];
    const float* x_proj_w   = (const float*)d_in[7];
    const float* dt_w       = (const float*)d_in[8];
    const float* dt_b       = (const float*)d_in[9];
    const float* A_log      = (const float*)d_in[10];
    const float* Dp         = (const float*)d_in[11];
    const float* out_proj_w = (const float*)d_in[12];
    const float* ro_w1      = (const float*)d_in[13];
    const float* ro_b1      = (const float*)d_in[14];
    const float* ro_w2      = (const float*)d_in[15];
    const float* ro_b2      = (const float*)d_in[16];
    const float* ro_w3      = (const float*)d_in[17];
    const float* ro_b3      = (const float*)d_in[18];

    float* out      = (float*)d_out;
    float* out_main = out;
    float* out_ro   = out + (size_t)BB*LL*V_SZ;
    float* out_hid  = out_ro + (size_t)BB*LL*V_SZ;

    float *px, *pxn, *pxz, *pxconv, *pdbc, *pdelta, *py, *ph1, *ph2, *pxf;
    cudaGetSymbolAddress((void**)&px,     g_x);
    cudaGetSymbolAddress((void**)&pxn,    g_xn);
    cudaGetSymbolAddress((void**)&pxz,    g_xz);
    cudaGetSymbolAddress((void**)&pxconv, g_xconv);
    cudaGetSymbolAddress((void**)&pdbc,   g_dbc);
    cudaGetSymbolAddress((void**)&pdelta, g_delta);
    cudaGetSymbolAddress((void**)&py,     g_y);
    cudaGetSymbolAddress((void**)&ph1,    g_h1);
    cudaGetSymbolAddress((void**)&ph2,    g_h2);
    cudaGetSymbolAddress((void**)&pxf,    g_xf);

    cudaFuncSetAttribute(mm3<0,0>, cudaFuncAttributeMaxDynamicSharedMemorySize, MM3_DSM);
    cudaFuncSetAttribute(mm3<1,0>, cudaFuncAttributeMaxDynamicSharedMemorySize, MM3_DSM);
    cudaFuncSetAttribute(mm3<0,1>, cudaFuncAttributeMaxDynamicSharedMemorySize, MM3_DSM);

    embed_kernel<<<(MM*DM + 255)/256, 256>>>(ids, emb, px);

    for (int l = 0; l < NL; l++) {
        rmsnorm_kernel<<<MM, 256>>>(px, norm_w + (size_t)l*DM, pxn);

        // xz = xn @ in_proj   (K=768, split 4 x 192 -> 6 chunks, grid 192)
        zero_kernel<<<(MM*2*DI + 255)/256, 256>>>(pxz, MM*2*DI);
        mm3<0,0><<<dim3(48, 4), 256, MM3_DSM>>>(
            pxn, DM, in_proj_w + (size_t)l*DM*2*DI, 2*DI, pxz, 2*DI,
            2*DI, 192, nullptr, 2);

        conv_kernel<<<(MM*DI + 255)/256, 256>>>(
            pxz, conv_w + (size_t)l*DI*DC, conv_b + (size_t)l*DI, pxconv);

        // dbc = xconv @ x_proj  (tiny: FFMA split-K=16)
        zero_kernel<<<(MM*80 + 255)/256, 256>>>(pdbc, MM*80);
        gemm_kernel<<<dim3(2, 2, 16), 256>>>(
            pxconv, x_proj_w + (size_t)l*DI*80, pdbc,
            MM, 80, DI, DI, 80, 80, nullptr, 2, 96);

        // delta_pre = dt @ dt_w + dt_b  (tiny: FFMA split-K=3, bias pre-init)
        binit_kernel<<<(MM*DI + 255)/256, 256>>>(pdelta, dt_b + (size_t)l*DI, MM, DI);
        gemm_kernel<<<dim3(24, 2, 3), 256>>>(
            pdbc, dt_w + (size_t)l*DTR*DI, pdelta,
            MM, DI, DTR, 80, DI, DI, nullptr, 2, 16);

        scan_kernel<<<dim3(DI/16, BB), 256>>>(
            pdbc, pdelta, pxconv, pxz,
            A_log + (size_t)l*DI*DS, Dp + (size_t)l*DI,
            py, out_hid + (size_t)l*MM*LBLK);

        // x += y @ out_proj   (K=1536, split 12 x 128 -> 4 chunks, grid 144)
        mm3<0,0><<<dim3(12, 12), 256, MM3_DSM>>>(
            py, DI, out_proj_w + (size_t)l*DI*DM, DM, px, DM,
            DM, 128, nullptr, 2);
    }

    // final norm + tied lm head (B = embed (V, DM) fp32 n-major)
    rmsnorm_kernel<<<MM, 256>>>(px, norm_f, pxf);
    mm3<1,0><<<dim3((V_SZ + 63)/64, 1), 256, MM3_DSM>>>(
        pxf, DM, emb, DM, out_main, V_SZ,
        V_SZ, DM, nullptr, 0);

    // readout: h1 = feat @ ro_w1 + b1; A = out_hid layered, split 24 x 4096 -> 128 chunks
    binit_kernel<<<(MM*ROH + 255)/256, 256>>>(ph1, ro_b1, MM, ROH);
    mm3<0,1><<<dim3(8, 24), 256, MM3_DSM>>>(
        out_hid, LBLK, ro_w1, ROH, ph1, ROH,
        ROH, 4096, nullptr, 2);

    // h2 = relu(h1) @ ro_w2 + b2  (tiny: FFMA, relu(A), atomic into bias-init)
    binit_kernel<<<(MM*(ROH/2) + 255)/256, 256>>>(ph2, ro_b2, MM, ROH/2);
    gemm_kernel<<<dim3(4, 2, 8), 256>>>(
        ph1, ro_w2, ph2, MM, ROH/2, ROH, ROH, ROH/2, ROH/2, nullptr, 3, 64);

    // readout_logits = relu(h2) @ ro_w3 + b3  (K=256 -> 8 chunks, relu(A), bias store)
    mm3<0,0><<<dim3((V_SZ + 63)/64, 1), 256, MM3_DSM>>>(
        ph2, ROH/2, ro_w3, V_SZ, out_ro, V_SZ,
        V_SZ, 256, ro_b3, 1);
}